// round 15
// baseline (speedup 1.0000x reference)
#include <cuda_runtime.h>
#include <cuda_fp16.h>
#include <cstdint>

#define BATCH 8
#define SEQ   4096
#define DIM   1024
#define RNK   64
#define KB    64
#define NIT   (SEQ/KB)

// ---------------- global scratch ----------------
__device__ __align__(16) __half g_P[BATCH * SEQ * RNK];
__device__ __align__(16) __half g_xh[(size_t)BATCH * SEQ * DIM];
__device__ __align__(16) __half g_Qt[RNK * DIM];          // Q^T * sqrt(log2e)/32, fp16
__device__ __align__(16) float  g_csum[BATCH * DIM];
__device__ __align__(16) float  g_cpart[32][BATCH * DIM];

// ---------------- helpers ----------------
__device__ __forceinline__ uint32_t smem_u32(const void* p) {
    uint32_t a;
    asm("{ .reg .u64 t; cvta.to.shared.u64 t, %1; cvt.u32.u64 %0, t; }" : "=r"(a) : "l"(p));
    return a;
}
__device__ __forceinline__ void ldsm4(uint32_t* r, uint32_t a) {
    asm volatile("ldmatrix.sync.aligned.m8n8.x4.shared.b16 {%0,%1,%2,%3}, [%4];"
        : "=r"(r[0]), "=r"(r[1]), "=r"(r[2]), "=r"(r[3]) : "r"(a));
}
__device__ __forceinline__ void ldsm4t(uint32_t* r, uint32_t a) {
    asm volatile("ldmatrix.sync.aligned.m8n8.x4.trans.shared.b16 {%0,%1,%2,%3}, [%4];"
        : "=r"(r[0]), "=r"(r[1]), "=r"(r[2]), "=r"(r[3]) : "r"(a));
}
__device__ __forceinline__ void mma16816(float* d, const uint32_t* a, const uint32_t* b) {
    asm volatile(
        "mma.sync.aligned.m16n8k16.row.col.f32.f16.f16.f32 "
        "{%0,%1,%2,%3}, {%4,%5,%6,%7}, {%8,%9}, {%0,%1,%2,%3};"
        : "+f"(d[0]), "+f"(d[1]), "+f"(d[2]), "+f"(d[3])
        : "r"(a[0]), "r"(a[1]), "r"(a[2]), "r"(a[3]), "r"(b[0]), "r"(b[1]));
}
// fp16-accumulator QK variant (saves registers): d = {row g pair, row g+8 pair}
__device__ __forceinline__ void mma16816h(uint32_t* d, const uint32_t* a, const uint32_t* b) {
    asm volatile(
        "mma.sync.aligned.m16n8k16.row.col.f16.f16.f16.f16 "
        "{%0,%1}, {%2,%3,%4,%5}, {%6,%7}, {%0,%1};"
        : "+r"(d[0]), "+r"(d[1])
        : "r"(a[0]), "r"(a[1]), "r"(a[2]), "r"(a[3]), "r"(b[0]), "r"(b[1]));
}
#define CP16(dst, src) \
    asm volatile("cp.async.cg.shared.global [%0], [%1], 16;" :: "r"(dst), "l"(src))
#define CP_COMMIT() asm volatile("cp.async.commit_group;" ::: "memory")
#define CP_WAIT0()  asm volatile("cp.async.wait_group 0;" ::: "memory")

__device__ __forceinline__ uint32_t packh(float a, float b) {
    __half2 h = __floats2half2_rn(a, b);
    return *(uint32_t*)&h;
}

// ---------------------------------------------------------------------------
// Fused cvt + csum: x fp32 -> fp16, and per-128-row-chunk column sums.
// ---------------------------------------------------------------------------
__global__ __launch_bounds__(256)
void cvtsum_kernel(const float* __restrict__ x) {
    const int t = threadIdx.x;
    const int sc = blockIdx.x, b = blockIdx.y;
    const float* xp = x + ((size_t)b * SEQ + (size_t)sc * 128) * DIM + 4 * t;
    __half* op = g_xh + ((size_t)b * SEQ + (size_t)sc * 128) * DIM + 4 * t;
    float s0 = 0.f, s1 = 0.f, s2 = 0.f, s3 = 0.f;
#pragma unroll 4
    for (int r = 0; r < 128; r++) {
        float4 v = *(const float4*)(xp + (size_t)r * DIM);
        s0 += v.x; s1 += v.y; s2 += v.z; s3 += v.w;
        *(uint2*)(op + (size_t)r * DIM) = make_uint2(packh(v.x, v.y), packh(v.z, v.w));
    }
    float* cp = g_cpart[sc] + b * DIM + 4 * t;
    cp[0] = s0; cp[1] = s1; cp[2] = s2; cp[3] = s3;
}
__global__ __launch_bounds__(256)
void csum2_kernel() {
    const int idx = blockIdx.x * 256 + threadIdx.x;
    float s = 0.f;
#pragma unroll
    for (int c = 0; c < 32; c++) s += g_cpart[c][idx];
    g_csum[idx] = s;
}

// ---------------------------------------------------------------------------
// qprep: Q -> g_Qt [64 n][1024 k] fp16, scaled by sqrt(log2 e)/32
// ---------------------------------------------------------------------------
__global__ __launch_bounds__(256)
void qprep_kernel(const float* __restrict__ Q) {
    __shared__ float ts[64][65];
    const int t = threadIdx.x;
    const int k0 = blockIdx.x * 64;
    const int r = t >> 2, cb = (t & 3) << 4;
    const float SC = 0.037535075274576556f;   // sqrt(log2 e) / 32
    const float* qp = Q + (size_t)(k0 + r) * RNK + cb;
#pragma unroll
    for (int m = 0; m < 4; m++) {
        float4 v = *(const float4*)(qp + 4 * m);
        ts[r][cb + 4 * m + 0] = v.x * SC;
        ts[r][cb + 4 * m + 1] = v.y * SC;
        ts[r][cb + 4 * m + 2] = v.z * SC;
        ts[r][cb + 4 * m + 3] = v.w * SC;
    }
    __syncthreads();
    __half* o = g_Qt + (size_t)r * DIM + k0 + cb;
#pragma unroll
    for (int m = 0; m < 2; m++) {
        uint32_t w[4];
#pragma unroll
        for (int p = 0; p < 4; p++)
            w[p] = packh(ts[cb + 8 * m + 2 * p][r], ts[cb + 8 * m + 2 * p + 1][r]);
        *(uint4*)(o + 8 * m) = make_uint4(w[0], w[1], w[2], w[3]);
    }
}

// ---------------------------------------------------------------------------
// projH: P = x_h @ Qt^T via HMMA
// ---------------------------------------------------------------------------
#define POFF_X 0
#define POFF_Q 32768
#define PSM_TOTAL 49152

__global__ __launch_bounds__(256, 2)
void projH_kernel() {
    extern __shared__ char sm[];
    const uint32_t smb = smem_u32(sm);
    const int t = threadIdx.x;
    const int warp = t >> 5, lane = t & 31;
    const int row0 = blockIdx.x * 128;
    const int q0 = warp * 16;
    const int tg = lane & 3, g = lane >> 2;
    const int i7 = lane & 7, grp = lane >> 3;

    {
#pragma unroll
        for (int m = 0; m < 4; m++) {
            int idx = t + 256 * m;
            int row = idx >> 3, ch = idx & 7;
            uint32_t dsw = row * 128 + (((uint32_t)(ch ^ (row & 7))) << 4);
            CP16(smb + POFF_X + dsw, g_xh + (size_t)(row0 + row) * DIM + ch * 8);
        }
#pragma unroll
        for (int m = 0; m < 2; m++) {
            int idx = t + 256 * m;
            int row = idx >> 3, ch = idx & 7;
            uint32_t dsw = row * 128 + (((uint32_t)(ch ^ (row & 7))) << 4);
            CP16(smb + POFF_Q + dsw, g_Qt + (size_t)row * DIM + ch * 8);
        }
        CP_COMMIT();
    }

    const uint32_t rowA = q0 + i7 + ((grp & 1) << 3);
    const uint32_t cselA = grp >> 1;
    const uint32_t rowB = i7 + ((grp >> 1) << 3);
    const uint32_t cselB = grp & 1;

    float S[8][4];
#pragma unroll
    for (int n = 0; n < 8; n++)
#pragma unroll
        for (int e = 0; e < 4; e++) S[n][e] = 0.f;

    for (int c = 0; c < 16; c++) {
        const int buf = c & 1;
        CP_WAIT0();
        __syncthreads();
        if (c + 1 < 16) {
            const int kc = (c + 1) * 64;
            const int bo = buf ^ 1;
#pragma unroll
            for (int m = 0; m < 4; m++) {
                int idx = t + 256 * m;
                int row = idx >> 3, ch = idx & 7;
                uint32_t dsw = row * 128 + (((uint32_t)(ch ^ (row & 7))) << 4);
                CP16(smb + POFF_X + bo * 16384 + dsw,
                     g_xh + (size_t)(row0 + row) * DIM + kc + ch * 8);
            }
#pragma unroll
            for (int m = 0; m < 2; m++) {
                int idx = t + 256 * m;
                int row = idx >> 3, ch = idx & 7;
                uint32_t dsw = row * 128 + (((uint32_t)(ch ^ (row & 7))) << 4);
                CP16(smb + POFF_Q + bo * 8192 + dsw,
                     g_Qt + (size_t)row * DIM + kc + ch * 8);
            }
            CP_COMMIT();
        }
        const uint32_t xb = smb + POFF_X + buf * 16384;
        const uint32_t qb = smb + POFF_Q + buf * 8192;
#pragma unroll
        for (int kt = 0; kt < 4; kt++) {
            uint32_t ah[4];
            ldsm4(ah, xb + rowA * 128 + ((((kt << 1) + cselA) ^ i7) << 4));
#pragma unroll
            for (int np = 0; np < 4; np++) {
                uint32_t bh[4];
                ldsm4(bh, qb + ((np << 4) + rowB) * 128
                          + ((((kt << 1) + cselB) ^ i7) << 4));
                mma16816(S[2 * np],     ah, bh + 0);
                mma16816(S[2 * np + 1], ah, bh + 2);
            }
        }
        __syncthreads();
    }

    const int row = row0 + q0 + g;
#pragma unroll
    for (int j = 0; j < 8; j++) {
        const int nb = (j >> 1) * 16 + (j & 1) * 8;
        *(uint32_t*)&g_P[(size_t)row * RNK + nb + 2 * tg] = packh(S[j][0], S[j][1]);
        *(uint32_t*)&g_P[(size_t)(row + 8) * RNK + nb + 2 * tg] = packh(S[j][2], S[j][3]);
    }
}

// ---------------------------------------------------------------------------
// Flash attention, 2 CTAs/SM. Warp tile 16q x 128d; KB=64; fp16-accum QK
// (register budget), h2exp2 softmax, fp32 PV accum.
// grid (32 qtiles, 8 d-slices, 8 batches), 256 threads.
// smem: PQ 16K | PK 2x8K | V 2x16K = 64K  ->  2 CTAs per SM
// ---------------------------------------------------------------------------
#define OFF_PQ   0
#define OFF_PK   16384
#define OFF_V    32768
#define SMEM_TOTAL 65536

__global__ __launch_bounds__(256, 2)
void attn_kernel(float* __restrict__ out) {
    extern __shared__ char sm[];
    const uint32_t smb = smem_u32(sm);
    const int t = threadIdx.x;
    const int warp = t >> 5, lane = t & 31;
    const int qb = blockIdx.x, z = blockIdx.y, b = blockIdx.z;
    const int q0 = warp * 16;
    const int tg = lane & 3, g = lane >> 2;
    const int i7 = lane & 7, grp = lane >> 3;

    const __half* pk_g = g_P + (size_t)b * SEQ * RNK;
    const __half* vh_g = g_xh + (size_t)b * SEQ * DIM + (size_t)z * 128;

    // ---- load Pq tile [128 q][64 r] into smem (swizzled) ----
#pragma unroll
    for (int m = 0; m < 4; m++) {
        int idx = t + 256 * m;
        int row = idx >> 3, ch = idx & 7;
        size_t src = ((size_t)b * SEQ + (size_t)qb * 128 + row) * RNK + ch * 8;
        uint32_t dst = row * 128 + (((uint32_t)(ch ^ (row & 7))) << 4);
        *(uint4*)(sm + OFF_PQ + dst) = *(const uint4*)(g_P + src);
    }
    // ---- prefetch tile 0 (64 keys) ----
    {
#pragma unroll
        for (int m = 0; m < 2; m++) {
            int idx = t + 256 * m;
            int row = idx >> 3, ch = idx & 7;
            uint32_t dsw = row * 128 + (((uint32_t)(ch ^ (row & 7))) << 4);
            CP16(smb + OFF_PK + dsw, pk_g + (size_t)row * RNK + ch * 8);
        }
#pragma unroll
        for (int m = 0; m < 4; m++) {
            int idx = t + 256 * m;
            int row = idx >> 4, ch = idx & 15;
            uint32_t dsw = row * 256 + (((uint32_t)(ch ^ (row & 7))) << 4);
            CP16(smb + OFF_V + dsw, vh_g + (size_t)row * DIM + ch * 8);
        }
        CP_COMMIT();
    }
    __syncthreads();

    // ---- hoist Pq A-fragments into registers ----
    const uint32_t rowA = q0 + i7 + ((grp & 1) << 3);
    const uint32_t cselA = grp >> 1;
    uint32_t aReg[4][4];
#pragma unroll
    for (int kt = 0; kt < 4; kt++)
        ldsm4(aReg[kt], smb + OFF_PQ + rowA * 128 + ((((kt << 1) + cselA) ^ i7) << 4));

    float Y[16][4];
#pragma unroll
    for (int n = 0; n < 16; n++)
#pragma unroll
        for (int e = 0; e < 4; e++) Y[n][e] = 0.f;
    float rl = 0.f, rh = 0.f;

    const uint32_t rowB = i7 + ((grp >> 1) << 3);
    const uint32_t cselB = grp & 1;
    const uint32_t rowV = i7 + ((grp & 1) << 3);
    const uint32_t cselV = grp >> 1;
    const __half2 ONE2 = __floats2half2_rn(1.f, 1.f);

    for (int it = 0; it < NIT; it++) {
        const int buf = it & 1;
        CP_WAIT0();
        __syncthreads();

        // prefetch tile it+1 (overlaps compute)
        if (it + 1 < NIT) {
            const int k0n = (it + 1) * KB;
            const int bo = buf ^ 1;
#pragma unroll
            for (int m = 0; m < 2; m++) {
                int idx = t + 256 * m;
                int row = idx >> 3, ch = idx & 7;
                uint32_t dsw = row * 128 + (((uint32_t)(ch ^ (row & 7))) << 4);
                CP16(smb + OFF_PK + bo * 8192 + dsw,
                     pk_g + (size_t)(k0n + row) * RNK + ch * 8);
            }
#pragma unroll
            for (int m = 0; m < 4; m++) {
                int idx = t + 256 * m;
                int row = idx >> 4, ch = idx & 15;
                uint32_t dsw = row * 256 + (((uint32_t)(ch ^ (row & 7))) << 4);
                CP16(smb + OFF_V + bo * 16384 + dsw,
                     vh_g + (size_t)(k0n + row) * DIM + ch * 8);
            }
            CP_COMMIT();
        }

        const uint32_t pkBase = smb + OFF_PK + buf * 8192;
        const uint32_t vBase  = smb + OFF_V  + buf * 16384;

        // ---- QK^T with fp16 accumulators ----
        uint32_t Sh[8][2];
#pragma unroll
        for (int n = 0; n < 8; n++) { Sh[n][0] = 0u; Sh[n][1] = 0u; }

#pragma unroll
        for (int kt = 0; kt < 4; kt++) {
#pragma unroll
            for (int np = 0; np < 4; np++) {
                uint32_t bh[4];
                ldsm4(bh, pkBase + ((np << 4) + rowB) * 128
                          + ((((kt << 1) + cselB) ^ i7) << 4));
                mma16816h(Sh[2 * np],     aReg[kt], bh + 0);
                mma16816h(Sh[2 * np + 1], aReg[kt], bh + 2);
            }
        }

        // ---- per-kt: h2exp2 softmax + PV mma (128 d) ----
        __half2 sl = __floats2half2_rn(0.f, 0.f);
        __half2 sh = __floats2half2_rn(0.f, 0.f);
#pragma unroll
        for (int kt = 0; kt < 4; kt++) {
            const int n0 = 2 * kt;
            __half2 p0 = h2exp2(*(__half2*)&Sh[n0][0]);
            __half2 p1 = h2exp2(*(__half2*)&Sh[n0][1]);
            __half2 p2 = h2exp2(*(__half2*)&Sh[n0 + 1][0]);
            __half2 p3 = h2exp2(*(__half2*)&Sh[n0 + 1][1]);
            sl = __hadd2(sl, __hadd2(p0, p2));
            sh = __hadd2(sh, __hadd2(p1, p3));
            __half2 q0h = __hsub2(p0, ONE2);
            __half2 q1h = __hsub2(p1, ONE2);
            __half2 q2h = __hsub2(p2, ONE2);
            __half2 q3h = __hsub2(p3, ONE2);
            uint32_t Ph[4];
            Ph[0] = *(uint32_t*)&q0h;
            Ph[1] = *(uint32_t*)&q1h;
            Ph[2] = *(uint32_t*)&q2h;
            Ph[3] = *(uint32_t*)&q3h;

            uint32_t vrow = vBase + ((kt << 4) + rowV) * 256;
#pragma unroll
            for (int np = 0; np < 8; np++) {
                uint32_t bh[4];
                ldsm4t(bh, vrow + ((((np << 1) + cselV) ^ i7) << 4));
                mma16816(Y[2 * np],     Ph, bh + 0);
                mma16816(Y[2 * np + 1], Ph, bh + 2);
            }
        }
        float2 fl = __half22float2(sl);
        float2 fh = __half22float2(sh);
        rl += fl.x + fl.y;
        rh += fh.x + fh.y;
    }

    // ---- single row-sum reduction at the end ----
    rl += __shfl_xor_sync(0xffffffffu, rl, 1);
    rl += __shfl_xor_sync(0xffffffffu, rl, 2);
    rh += __shfl_xor_sync(0xffffffffu, rh, 1);
    rh += __shfl_xor_sync(0xffffffffu, rh, 2);

    // ---- epilogue: y = (csum + Ydot) / l ----
    const float il = 1.0f / rl;
    const float ih = 1.0f / rh;
    const int rlo = qb * 128 + q0 + g;
    const float* cs_base = g_csum + b * DIM + z * 128 + 2 * tg;
    float* o_lo = out + ((size_t)b * SEQ + rlo) * DIM + (size_t)z * 128 + 2 * tg;
    float* o_hi = o_lo + (size_t)8 * DIM;
#pragma unroll
    for (int n = 0; n < 16; n++) {
        float2 cs = *(const float2*)(cs_base + 8 * n);
        float2 p;
        p.x = (Y[n][0] + cs.x) * il; p.y = (Y[n][1] + cs.y) * il;
        *(float2*)(o_lo + 8 * n) = p;
        p.x = (Y[n][2] + cs.x) * ih; p.y = (Y[n][3] + cs.y) * ih;
        *(float2*)(o_hi + 8 * n) = p;
    }
}

// ---------------------------------------------------------------------------
extern "C" void kernel_launch(void* const* d_in, const int* in_sizes, int n_in,
                              void* d_out, int out_size) {
    const float* x = (const float*)d_in[0];
    const float* Q = (const float*)d_in[1];
    float* out = (float*)d_out;

    cudaFuncSetAttribute(attn_kernel, cudaFuncAttributeMaxDynamicSharedMemorySize,
                         SMEM_TOTAL);
    cudaFuncSetAttribute(projH_kernel, cudaFuncAttributeMaxDynamicSharedMemorySize,
                         PSM_TOTAL);

    cvtsum_kernel<<<dim3(SEQ / 128, BATCH), 256>>>(x);
    qprep_kernel<<<DIM / 64, 256>>>(Q);
    projH_kernel<<<BATCH * SEQ / 128, 256, PSM_TOTAL>>>();
    csum2_kernel<<<BATCH * DIM / 256, 256>>>();
    attn_kernel<<<dim3(SEQ / 128, DIM / 128, BATCH), 256, SMEM_TOTAL>>>(out);
}

// round 16
// speedup vs baseline: 1.2498x; 1.2498x over previous
#include <cuda_runtime.h>
#include <cuda_fp16.h>
#include <cstdint>

#define BATCH 8
#define SEQ   4096
#define DIM   1024
#define RNK   64

// ---------------- global scratch ----------------
__device__ __align__(16) __half g_P[BATCH * SEQ * RNK];
__device__ __align__(16) __half g_xh[(size_t)BATCH * SEQ * DIM];
__device__ __align__(16) __half g_Qt[RNK * DIM];          // Q^T * sqrt(log2e)/32, fp16
__device__ __align__(16) __half g_PM[(size_t)BATCH * SEQ * SEQ]; // (p-1) fp16, [b][qb][q][k]
__device__ __align__(16) float  g_L[BATCH * SEQ];
__device__ __align__(16) float  g_csum[BATCH * DIM];
__device__ __align__(16) float  g_cpart[32][BATCH * DIM];

// ---------------- helpers ----------------
__device__ __forceinline__ uint32_t smem_u32(const void* p) {
    uint32_t a;
    asm("{ .reg .u64 t; cvta.to.shared.u64 t, %1; cvt.u32.u64 %0, t; }" : "=r"(a) : "l"(p));
    return a;
}
__device__ __forceinline__ void ldsm4(uint32_t* r, uint32_t a) {
    asm volatile("ldmatrix.sync.aligned.m8n8.x4.shared.b16 {%0,%1,%2,%3}, [%4];"
        : "=r"(r[0]), "=r"(r[1]), "=r"(r[2]), "=r"(r[3]) : "r"(a));
}
__device__ __forceinline__ void ldsm4t(uint32_t* r, uint32_t a) {
    asm volatile("ldmatrix.sync.aligned.m8n8.x4.trans.shared.b16 {%0,%1,%2,%3}, [%4];"
        : "=r"(r[0]), "=r"(r[1]), "=r"(r[2]), "=r"(r[3]) : "r"(a));
}
__device__ __forceinline__ void mma16816(float* d, const uint32_t* a, const uint32_t* b) {
    asm volatile(
        "mma.sync.aligned.m16n8k16.row.col.f32.f16.f16.f32 "
        "{%0,%1,%2,%3}, {%4,%5,%6,%7}, {%8,%9}, {%0,%1,%2,%3};"
        : "+f"(d[0]), "+f"(d[1]), "+f"(d[2]), "+f"(d[3])
        : "r"(a[0]), "r"(a[1]), "r"(a[2]), "r"(a[3]), "r"(b[0]), "r"(b[1]));
}
#define CP16(dst, src) \
    asm volatile("cp.async.cg.shared.global [%0], [%1], 16;" :: "r"(dst), "l"(src))
#define CP_COMMIT() asm volatile("cp.async.commit_group;" ::: "memory")
#define CP_WAIT0()  asm volatile("cp.async.wait_group 0;" ::: "memory")

__device__ __forceinline__ uint32_t packh(float a, float b) {
    __half2 h = __floats2half2_rn(a, b);
    return *(uint32_t*)&h;
}

// ---------------------------------------------------------------------------
// Fused cvt + csum: x fp32 -> fp16, and per-128-row-chunk column sums.
// ---------------------------------------------------------------------------
__global__ __launch_bounds__(256)
void cvtsum_kernel(const float* __restrict__ x) {
    const int t = threadIdx.x;
    const int sc = blockIdx.x, b = blockIdx.y;
    const float* xp = x + ((size_t)b * SEQ + (size_t)sc * 128) * DIM + 4 * t;
    __half* op = g_xh + ((size_t)b * SEQ + (size_t)sc * 128) * DIM + 4 * t;
    float s0 = 0.f, s1 = 0.f, s2 = 0.f, s3 = 0.f;
#pragma unroll 4
    for (int r = 0; r < 128; r++) {
        float4 v = *(const float4*)(xp + (size_t)r * DIM);
        s0 += v.x; s1 += v.y; s2 += v.z; s3 += v.w;
        *(uint2*)(op + (size_t)r * DIM) = make_uint2(packh(v.x, v.y), packh(v.z, v.w));
    }
    float* cp = g_cpart[sc] + b * DIM + 4 * t;
    cp[0] = s0; cp[1] = s1; cp[2] = s2; cp[3] = s3;
}
__global__ __launch_bounds__(256)
void csum2_kernel() {
    const int idx = blockIdx.x * 256 + threadIdx.x;
    float s = 0.f;
#pragma unroll
    for (int c = 0; c < 32; c++) s += g_cpart[c][idx];
    g_csum[idx] = s;
}

// ---------------------------------------------------------------------------
// qprep: Q -> g_Qt [64 n][1024 k] fp16, scaled by sqrt(log2 e)/32
// ---------------------------------------------------------------------------
__global__ __launch_bounds__(256)
void qprep_kernel(const float* __restrict__ Q) {
    __shared__ float ts[64][65];
    const int t = threadIdx.x;
    const int k0 = blockIdx.x * 64;
    const int r = t >> 2, cb = (t & 3) << 4;
    const float SC = 0.037535075274576556f;   // sqrt(log2 e) / 32
    const float* qp = Q + (size_t)(k0 + r) * RNK + cb;
#pragma unroll
    for (int m = 0; m < 4; m++) {
        float4 v = *(const float4*)(qp + 4 * m);
        ts[r][cb + 4 * m + 0] = v.x * SC;
        ts[r][cb + 4 * m + 1] = v.y * SC;
        ts[r][cb + 4 * m + 2] = v.z * SC;
        ts[r][cb + 4 * m + 3] = v.w * SC;
    }
    __syncthreads();
    __half* o = g_Qt + (size_t)r * DIM + k0 + cb;
#pragma unroll
    for (int m = 0; m < 2; m++) {
        uint32_t w[4];
#pragma unroll
        for (int p = 0; p < 4; p++)
            w[p] = packh(ts[cb + 8 * m + 2 * p][r], ts[cb + 8 * m + 2 * p + 1][r]);
        *(uint4*)(o + 8 * m) = make_uint4(w[0], w[1], w[2], w[3]);
    }
}

// ---------------------------------------------------------------------------
// projH: P = x_h @ Qt^T via HMMA
// ---------------------------------------------------------------------------
#define POFF_X 0
#define POFF_Q 32768
#define PSM_TOTAL 49152

__global__ __launch_bounds__(256, 2)
void projH_kernel() {
    extern __shared__ char sm[];
    const uint32_t smb = smem_u32(sm);
    const int t = threadIdx.x;
    const int warp = t >> 5, lane = t & 31;
    const int row0 = blockIdx.x * 128;
    const int q0 = warp * 16;
    const int tg = lane & 3, g = lane >> 2;
    const int i7 = lane & 7, grp = lane >> 3;

    {
#pragma unroll
        for (int m = 0; m < 4; m++) {
            int idx = t + 256 * m;
            int row = idx >> 3, ch = idx & 7;
            uint32_t dsw = row * 128 + (((uint32_t)(ch ^ (row & 7))) << 4);
            CP16(smb + POFF_X + dsw, g_xh + (size_t)(row0 + row) * DIM + ch * 8);
        }
#pragma unroll
        for (int m = 0; m < 2; m++) {
            int idx = t + 256 * m;
            int row = idx >> 3, ch = idx & 7;
            uint32_t dsw = row * 128 + (((uint32_t)(ch ^ (row & 7))) << 4);
            CP16(smb + POFF_Q + dsw, g_Qt + (size_t)row * DIM + ch * 8);
        }
        CP_COMMIT();
    }

    const uint32_t rowA = q0 + i7 + ((grp & 1) << 3);
    const uint32_t cselA = grp >> 1;
    const uint32_t rowB = i7 + ((grp >> 1) << 3);
    const uint32_t cselB = grp & 1;

    float S[8][4];
#pragma unroll
    for (int n = 0; n < 8; n++)
#pragma unroll
        for (int e = 0; e < 4; e++) S[n][e] = 0.f;

    for (int c = 0; c < 16; c++) {
        const int buf = c & 1;
        CP_WAIT0();
        __syncthreads();
        if (c + 1 < 16) {
            const int kc = (c + 1) * 64;
            const int bo = buf ^ 1;
#pragma unroll
            for (int m = 0; m < 4; m++) {
                int idx = t + 256 * m;
                int row = idx >> 3, ch = idx & 7;
                uint32_t dsw = row * 128 + (((uint32_t)(ch ^ (row & 7))) << 4);
                CP16(smb + POFF_X + bo * 16384 + dsw,
                     g_xh + (size_t)(row0 + row) * DIM + kc + ch * 8);
            }
#pragma unroll
            for (int m = 0; m < 2; m++) {
                int idx = t + 256 * m;
                int row = idx >> 3, ch = idx & 7;
                uint32_t dsw = row * 128 + (((uint32_t)(ch ^ (row & 7))) << 4);
                CP16(smb + POFF_Q + bo * 8192 + dsw,
                     g_Qt + (size_t)row * DIM + kc + ch * 8);
            }
            CP_COMMIT();
        }
        const uint32_t xb = smb + POFF_X + buf * 16384;
        const uint32_t qb = smb + POFF_Q + buf * 8192;
#pragma unroll
        for (int kt = 0; kt < 4; kt++) {
            uint32_t ah[4];
            ldsm4(ah, xb + rowA * 128 + ((((kt << 1) + cselA) ^ i7) << 4));
#pragma unroll
            for (int np = 0; np < 4; np++) {
                uint32_t bh[4];
                ldsm4(bh, qb + ((np << 4) + rowB) * 128
                          + ((((kt << 1) + cselB) ^ i7) << 4));
                mma16816(S[2 * np],     ah, bh + 0);
                mma16816(S[2 * np + 1], ah, bh + 2);
            }
        }
        __syncthreads();
    }

    const int row = row0 + q0 + g;
#pragma unroll
    for (int j = 0; j < 8; j++) {
        const int nb = (j >> 1) * 16 + (j & 1) * 8;
        *(uint32_t*)&g_P[(size_t)row * RNK + nb + 2 * tg] = packh(S[j][0], S[j][1]);
        *(uint32_t*)&g_P[(size_t)(row + 8) * RNK + nb + 2 * tg] = packh(S[j][2], S[j][3]);
    }
}

// ---------------------------------------------------------------------------
// Phase A: probs. grid (32 qtiles, 8 batches). Computes S = Pq Pk^T once,
// softmax via h2exp2, stores (p-1) fp16 to g_PM and row sums to g_L.
// smem: PQ 16K | PK 2x8K = 32K
// ---------------------------------------------------------------------------
#define AOFF_PQ 0
#define AOFF_PK 16384
#define ASM_TOTAL 32768

__global__ __launch_bounds__(256, 2)
void probs_kernel() {
    extern __shared__ char sm[];
    const uint32_t smb = smem_u32(sm);
    const int t = threadIdx.x;
    const int warp = t >> 5, lane = t & 31;
    const int qb = blockIdx.x, b = blockIdx.y;
    const int q0 = warp * 16;
    const int tg = lane & 3, g = lane >> 2;
    const int i7 = lane & 7, grp = lane >> 3;

    const __half* pk_g = g_P + (size_t)b * SEQ * RNK;
    __half* pm_g = g_PM + ((size_t)b * 32 + qb) * 128 * SEQ;

    // ---- load Pq tile ----
#pragma unroll
    for (int m = 0; m < 4; m++) {
        int idx = t + 256 * m;
        int row = idx >> 3, ch = idx & 7;
        size_t src = ((size_t)b * SEQ + (size_t)qb * 128 + row) * RNK + ch * 8;
        uint32_t dst = row * 128 + (((uint32_t)(ch ^ (row & 7))) << 4);
        *(uint4*)(sm + AOFF_PQ + dst) = *(const uint4*)(g_P + src);
    }
    // ---- prefetch PK tile 0 ----
#pragma unroll
    for (int m = 0; m < 2; m++) {
        int idx = t + 256 * m;
        int row = idx >> 3, ch = idx & 7;
        uint32_t dsw = row * 128 + (((uint32_t)(ch ^ (row & 7))) << 4);
        CP16(smb + AOFF_PK + dsw, pk_g + (size_t)row * RNK + ch * 8);
    }
    CP_COMMIT();
    __syncthreads();

    const uint32_t rowA = q0 + i7 + ((grp & 1) << 3);
    const uint32_t cselA = grp >> 1;
    uint32_t aReg[4][4];
#pragma unroll
    for (int kt = 0; kt < 4; kt++)
        ldsm4(aReg[kt], smb + AOFF_PQ + rowA * 128 + ((((kt << 1) + cselA) ^ i7) << 4));

    const uint32_t rowB = i7 + ((grp >> 1) << 3);
    const uint32_t cselB = grp & 1;
    float rl = 0.f, rh = 0.f;
    const __half2 ONE2 = __floats2half2_rn(1.f, 1.f);
    __half* pm_rg  = pm_g + (size_t)(q0 + g) * SEQ;
    __half* pm_rg8 = pm_g + (size_t)(q0 + g + 8) * SEQ;

    for (int it = 0; it < 64; it++) {
        const int buf = it & 1;
        const int k0 = it * 64;
        CP_WAIT0();
        __syncthreads();
        if (it + 1 < 64) {
            const int k0n = (it + 1) * 64;
            const int bo = buf ^ 1;
#pragma unroll
            for (int m = 0; m < 2; m++) {
                int idx = t + 256 * m;
                int row = idx >> 3, ch = idx & 7;
                uint32_t dsw = row * 128 + (((uint32_t)(ch ^ (row & 7))) << 4);
                CP16(smb + AOFF_PK + bo * 8192 + dsw,
                     pk_g + (size_t)(k0n + row) * RNK + ch * 8);
            }
            CP_COMMIT();
        }

        float S[8][4];
#pragma unroll
        for (int n = 0; n < 8; n++)
#pragma unroll
            for (int e = 0; e < 4; e++) S[n][e] = 0.f;

        const uint32_t pkBase = smb + AOFF_PK + buf * 8192;
#pragma unroll
        for (int kt = 0; kt < 4; kt++) {
#pragma unroll
            for (int np = 0; np < 4; np++) {
                uint32_t bh[4];
                ldsm4(bh, pkBase + ((np << 4) + rowB) * 128
                          + ((((kt << 1) + cselB) ^ i7) << 4));
                mma16816(S[2 * np],     aReg[kt], bh + 0);
                mma16816(S[2 * np + 1], aReg[kt], bh + 2);
            }
        }

        // softmax + store (p-1) fp16
#pragma unroll
        for (int kt = 0; kt < 4; kt++) {
            const int n0 = 2 * kt;
            __half2 t0 = __floats2half2_rn(S[n0][0],     S[n0][1]);
            __half2 t1 = __floats2half2_rn(S[n0][2],     S[n0][3]);
            __half2 t2 = __floats2half2_rn(S[n0 + 1][0], S[n0 + 1][1]);
            __half2 t3 = __floats2half2_rn(S[n0 + 1][2], S[n0 + 1][3]);
            __half2 p0 = h2exp2(t0);
            __half2 p1 = h2exp2(t1);
            __half2 p2 = h2exp2(t2);
            __half2 p3 = h2exp2(t3);
            float2 f0 = __half22float2(p0);
            float2 f1 = __half22float2(p1);
            float2 f2 = __half22float2(p2);
            float2 f3 = __half22float2(p3);
            rl += (f0.x + f0.y) + (f2.x + f2.y);
            rh += (f1.x + f1.y) + (f3.x + f3.y);
            __half2 q0h = __hsub2(p0, ONE2);
            __half2 q1h = __hsub2(p1, ONE2);
            __half2 q2h = __hsub2(p2, ONE2);
            __half2 q3h = __hsub2(p3, ONE2);
            const int cb = k0 + kt * 16 + 2 * tg;
            *(uint32_t*)(pm_rg  + cb)     = *(uint32_t*)&q0h;
            *(uint32_t*)(pm_rg8 + cb)     = *(uint32_t*)&q1h;
            *(uint32_t*)(pm_rg  + cb + 8) = *(uint32_t*)&q2h;
            *(uint32_t*)(pm_rg8 + cb + 8) = *(uint32_t*)&q3h;
        }
    }

    rl += __shfl_xor_sync(0xffffffffu, rl, 1);
    rl += __shfl_xor_sync(0xffffffffu, rl, 2);
    rh += __shfl_xor_sync(0xffffffffu, rh, 1);
    rh += __shfl_xor_sync(0xffffffffu, rh, 2);
    if (tg == 0) {
        g_L[b * SEQ + qb * 128 + q0 + g] = rl;
        g_L[b * SEQ + qb * 128 + q0 + g + 8] = rh;
    }
}

// ---------------------------------------------------------------------------
// Phase B: PV GEMM. Y = PM1 @ V, then y = (csum + Y) / l.
// grid (4 d-slices, 32 qtiles, 8 batches) — z fastest for PM L2 reuse.
// smem: PM 2x32K | V 2x64K = 192K. KB=128, two 64-k subtiles.
// ---------------------------------------------------------------------------
#define BOFF_PM 0
#define BOFF_V  65536
#define BSM_TOTAL 196608
#define BKB 128
#define BNIT (SEQ/BKB)

__global__ __launch_bounds__(256, 1)
void pv_kernel(float* __restrict__ out) {
    extern __shared__ char sm[];
    const uint32_t smb = smem_u32(sm);
    const int t = threadIdx.x;
    const int warp = t >> 5, lane = t & 31;
    const int z = blockIdx.x, qb = blockIdx.y, b = blockIdx.z;
    const int q0 = warp * 16;
    const int tg = lane & 3, g = lane >> 2;
    const int i7 = lane & 7, grp = lane >> 3;

    const __half* pm_g = g_PM + ((size_t)b * 32 + qb) * 128 * SEQ;
    const __half* vh_g = g_xh + (size_t)b * SEQ * DIM + (size_t)z * 256;

    // ---- prefetch tile 0 ----
    {
#pragma unroll
        for (int sub = 0; sub < 2; sub++)
#pragma unroll
            for (int m = 0; m < 4; m++) {
                int idx = t + 256 * m;
                int row = idx >> 3, ch = idx & 7;
                uint32_t dsw = sub * 16384 + row * 128 + (((uint32_t)(ch ^ (row & 7))) << 4);
                CP16(smb + BOFF_PM + dsw, pm_g + (size_t)row * SEQ + sub * 64 + ch * 8);
            }
#pragma unroll
        for (int m = 0; m < 16; m++) {
            int idx = t + 256 * m;
            int row = idx >> 5, ch = idx & 31;
            uint32_t dsw = row * 512 + (((uint32_t)(ch ^ (row & 7))) << 4);
            CP16(smb + BOFF_V + dsw, vh_g + (size_t)row * DIM + ch * 8);
        }
        CP_COMMIT();
    }

    float Y[32][4];
#pragma unroll
    for (int n = 0; n < 32; n++)
#pragma unroll
        for (int e = 0; e < 4; e++) Y[n][e] = 0.f;

    const uint32_t rowA = q0 + i7 + ((grp & 1) << 3);
    const uint32_t cselA = grp >> 1;
    const uint32_t rowV = i7 + ((grp & 1) << 3);
    const uint32_t cselV = grp >> 1;

    for (int it = 0; it < BNIT; it++) {
        const int buf = it & 1;
        CP_WAIT0();
        __syncthreads();

        if (it + 1 < BNIT) {
            const int k0n = (it + 1) * BKB;
            const int bo = buf ^ 1;
#pragma unroll
            for (int sub = 0; sub < 2; sub++)
#pragma unroll
                for (int m = 0; m < 4; m++) {
                    int idx = t + 256 * m;
                    int row = idx >> 3, ch = idx & 7;
                    uint32_t dsw = sub * 16384 + row * 128
                                 + (((uint32_t)(ch ^ (row & 7))) << 4);
                    CP16(smb + BOFF_PM + bo * 32768 + dsw,
                         pm_g + (size_t)row * SEQ + k0n + sub * 64 + ch * 8);
                }
#pragma unroll
            for (int m = 0; m < 16; m++) {
                int idx = t + 256 * m;
                int row = idx >> 5, ch = idx & 31;
                uint32_t dsw = row * 512 + (((uint32_t)(ch ^ (row & 7))) << 4);
                CP16(smb + BOFF_V + bo * 65536 + dsw,
                     vh_g + (size_t)(k0n + row) * DIM + ch * 8);
            }
            CP_COMMIT();
        }

#pragma unroll
        for (int sub = 0; sub < 2; sub++) {
            const uint32_t pmBase = smb + BOFF_PM + buf * 32768 + sub * 16384;
            const uint32_t vBase  = smb + BOFF_V  + buf * 65536 + sub * 32768;
#pragma unroll
            for (int kt = 0; kt < 4; kt++) {
                uint32_t Ph[4];
                ldsm4(Ph, pmBase + rowA * 128 + ((((kt << 1) + cselA) ^ i7) << 4));
                uint32_t vrow = vBase + ((kt << 4) + rowV) * 512;
#pragma unroll
                for (int np = 0; np < 16; np++) {
                    uint32_t bh[4];
                    ldsm4t(bh, vrow + ((((np << 1) + cselV) ^ i7) << 4));
                    mma16816(Y[2 * np],     Ph, bh + 0);
                    mma16816(Y[2 * np + 1], Ph, bh + 2);
                }
            }
        }
    }

    // ---- epilogue: y = (csum + Ydot) / l ----
    const int rlo = qb * 128 + q0 + g;
    const float il = 1.0f / g_L[b * SEQ + rlo];
    const float ih = 1.0f / g_L[b * SEQ + rlo + 8];
    const float* cs_base = g_csum + b * DIM + z * 256 + 2 * tg;
    float* o_lo = out + ((size_t)b * SEQ + rlo) * DIM + (size_t)z * 256 + 2 * tg;
    float* o_hi = o_lo + (size_t)8 * DIM;
#pragma unroll
    for (int n = 0; n < 32; n++) {
        float2 cs = *(const float2*)(cs_base + 8 * n);
        float2 p;
        p.x = (Y[n][0] + cs.x) * il; p.y = (Y[n][1] + cs.y) * il;
        *(float2*)(o_lo + 8 * n) = p;
        p.x = (Y[n][2] + cs.x) * ih; p.y = (Y[n][3] + cs.y) * ih;
        *(float2*)(o_hi + 8 * n) = p;
    }
}

// ---------------------------------------------------------------------------
extern "C" void kernel_launch(void* const* d_in, const int* in_sizes, int n_in,
                              void* d_out, int out_size) {
    const float* x = (const float*)d_in[0];
    const float* Q = (const float*)d_in[1];
    float* out = (float*)d_out;

    cudaFuncSetAttribute(projH_kernel, cudaFuncAttributeMaxDynamicSharedMemorySize,
                         PSM_TOTAL);
    cudaFuncSetAttribute(probs_kernel, cudaFuncAttributeMaxDynamicSharedMemorySize,
                         ASM_TOTAL);
    cudaFuncSetAttribute(pv_kernel, cudaFuncAttributeMaxDynamicSharedMemorySize,
                         BSM_TOTAL);

    cvtsum_kernel<<<dim3(SEQ / 128, BATCH), 256>>>(x);
    qprep_kernel<<<DIM / 64, 256>>>(Q);
    projH_kernel<<<BATCH * SEQ / 128, 256, PSM_TOTAL>>>();
    csum2_kernel<<<BATCH * DIM / 256, 256>>>();
    probs_kernel<<<dim3(SEQ / 128, BATCH), 256, ASM_TOTAL>>>();
    pv_kernel<<<dim3(DIM / 256, SEQ / 128, BATCH), 256, BSM_TOTAL>>>(out);
}